// round 2
// baseline (speedup 1.0000x reference)
#include <cuda_runtime.h>
#include <cuda_bf16.h>
#include <math.h>

// Problem constants (fixed shapes per reference)
#define NMAX 100000
#define EMAX 1600000
#define FIN  256
#define HID  64
#define KCH  10

// ---------------- static device scratch (no allocations allowed) -------------
__device__ float g_buf0[NMAX * HID];
__device__ float g_buf1[NMAX * HID];
__device__ float g_buf2[NMAX * HID];

__device__ int   g_deg[NMAX];
__device__ int   g_cnt[NMAX];
__device__ float g_dis[NMAX];
__device__ int   g_excl[NMAX];
__device__ int   g_rowptr[NMAX + 1];
__device__ int   g_cursor[NMAX];
__device__ int   g_blksum[256];
__device__ int   g_csr_src[EMAX];
__device__ float g_csr_w[EMAX];
__device__ float g_coe[KCH + 1];

__device__ __forceinline__ float* bufptr(int i) {
    return (i == 0) ? g_buf0 : ((i == 1) ? g_buf1 : g_buf2);
}

// ---------------- MLP: h = relu(x@W1 + b1) @ W2 + b2  -> g_buf0 -------------
// Block: 64 rows, 256 threads (16x16), 4x4 micro-tile per thread.
__global__ __launch_bounds__(256) void mlp_kernel(
    const float* __restrict__ x,
    const float* __restrict__ W1, const float* __restrict__ b1,
    const float* __restrict__ W2, const float* __restrict__ b2,
    int n)
{
    __shared__ float As[16][68];   // [kk][row]
    __shared__ float Ws[16][68];   // [kk][col]
    __shared__ float Hst[64][68];  // [c][row]  (transposed hidden)
    __shared__ float W2s[64][68];  // [c][col]

    const int tid = threadIdx.x;
    const int tx = tid & 15, ty = tid >> 4;
    const int row0 = blockIdx.x * 64;

    // stage W2 fully
    for (int i = tid; i < 64 * 64; i += 256)
        W2s[i >> 6][i & 63] = W2[i];

    float acc[4][4];
    #pragma unroll
    for (int i = 0; i < 4; i++)
        #pragma unroll
        for (int j = 0; j < 4; j++) acc[i][j] = 0.f;

    for (int k0 = 0; k0 < FIN; k0 += 16) {
        // load A tile (64 rows x 16 k), transposed into As[kk][r]
        {
            int kk = tid & 15, rb = tid >> 4;
            #pragma unroll
            for (int s = 0; s < 4; s++) {
                int r = rb + s * 16;
                int gr = row0 + r;
                As[kk][r] = (gr < n) ? x[(size_t)gr * FIN + k0 + kk] : 0.f;
            }
        }
        // load W1 tile (16 x 64)
        {
            int nn = tid & 63, kb = tid >> 6;
            #pragma unroll
            for (int s = 0; s < 4; s++) {
                int kw = kb + s * 4;
                Ws[kw][nn] = W1[(size_t)(k0 + kw) * HID + nn];
            }
        }
        __syncthreads();
        #pragma unroll
        for (int kk = 0; kk < 16; kk++) {
            float4 a4 = *(const float4*)(&As[kk][ty * 4]);
            float4 b4 = *(const float4*)(&Ws[kk][tx * 4]);
            float av[4] = {a4.x, a4.y, a4.z, a4.w};
            float bv[4] = {b4.x, b4.y, b4.z, b4.w};
            #pragma unroll
            for (int i = 0; i < 4; i++)
                #pragma unroll
                for (int j = 0; j < 4; j++)
                    acc[i][j] = fmaf(av[i], bv[j], acc[i][j]);
        }
        __syncthreads();
    }

    // bias + relu, store transposed hidden
    {
        float4 bb = *(const float4*)(&b1[tx * 4]);
        float bv[4] = {bb.x, bb.y, bb.z, bb.w};
        #pragma unroll
        for (int i = 0; i < 4; i++)
            #pragma unroll
            for (int j = 0; j < 4; j++) {
                float v = acc[i][j] + bv[j];
                Hst[tx * 4 + j][ty * 4 + i] = fmaxf(v, 0.f);
            }
    }
    __syncthreads();

    float acc2[4][4];
    #pragma unroll
    for (int i = 0; i < 4; i++)
        #pragma unroll
        for (int j = 0; j < 4; j++) acc2[i][j] = 0.f;

    #pragma unroll 8
    for (int c = 0; c < 64; c++) {
        float4 a4 = *(const float4*)(&Hst[c][ty * 4]);
        float4 b4 = *(const float4*)(&W2s[c][tx * 4]);
        float av[4] = {a4.x, a4.y, a4.z, a4.w};
        float bv[4] = {b4.x, b4.y, b4.z, b4.w};
        #pragma unroll
        for (int i = 0; i < 4; i++)
            #pragma unroll
            for (int j = 0; j < 4; j++)
                acc2[i][j] = fmaf(av[i], bv[j], acc2[i][j]);
    }

    {
        float4 bb = *(const float4*)(&b2[tx * 4]);
        float bv[4] = {bb.x, bb.y, bb.z, bb.w};
        #pragma unroll
        for (int i = 0; i < 4; i++) {
            int gr = row0 + ty * 4 + i;
            if (gr < n) {
                float4 o;
                o.x = acc2[i][0] + bv[0];
                o.y = acc2[i][1] + bv[1];
                o.z = acc2[i][2] + bv[2];
                o.w = acc2[i][3] + bv[3];
                *(float4*)(&g_buf0[(size_t)gr * HID + tx * 4]) = o;
            }
        }
    }
}

// ---------------- graph preprocessing ---------------------------------------
__global__ void zero_kernel(int n) {
    int i = blockIdx.x * blockDim.x + threadIdx.x;
    if (i < n) { g_deg[i] = 0; g_cnt[i] = 0; }
}

// edge_index is int32 (JAX x64 disabled downgrades int64 -> int32).
__global__ void hist_kernel(const int* __restrict__ ei, int e, int n) {
    int i = blockIdx.x * blockDim.x + threadIdx.x;
    if (i < e) {
        int r = ei[i];
        int c = ei[(size_t)e + i];
        if ((unsigned)r < (unsigned)n) atomicAdd(&g_deg[r], 1);
        if ((unsigned)c < (unsigned)n) atomicAdd(&g_cnt[c], 1);
    }
}

__global__ void dis_kernel(int n) {
    int i = blockIdx.x * blockDim.x + threadIdx.x;
    if (i < n) {
        int d = g_deg[i];
        g_dis[i] = (d > 0) ? rsqrtf((float)d) : 0.f;
    }
}

// exclusive scan pass 1: per-1024 chunk, 256 threads x 4 elems
__global__ __launch_bounds__(256) void scan1_kernel(int n) {
    __shared__ int wsum[8];
    int tid = threadIdx.x;
    int lane = tid & 31, wid = tid >> 5;
    int base = blockIdx.x * 1024 + tid * 4;
    int v[4];
    #pragma unroll
    for (int j = 0; j < 4; j++)
        v[j] = (base + j < n) ? g_cnt[base + j] : 0;
    int tsum = v[0] + v[1] + v[2] + v[3];

    int sc = tsum;
    #pragma unroll
    for (int off = 1; off < 32; off <<= 1) {
        int t = __shfl_up_sync(0xffffffffu, sc, off);
        if (lane >= off) sc += t;
    }
    if (lane == 31) wsum[wid] = sc;
    __syncthreads();
    if (tid == 0) {
        int a = 0;
        #pragma unroll
        for (int i = 0; i < 8; i++) { int t = wsum[i]; wsum[i] = a; a += t; }
    }
    __syncthreads();
    int run = (sc - tsum) + wsum[wid];
    #pragma unroll
    for (int j = 0; j < 4; j++) {
        if (base + j < n) g_excl[base + j] = run;
        run += v[j];
    }
    if (tid == 255) g_blksum[blockIdx.x] = run;
}

__global__ void scan2_kernel(int nblk) {
    __shared__ int s[256];
    int tid = threadIdx.x;
    if (tid < nblk) s[tid] = g_blksum[tid];
    __syncthreads();
    if (tid == 0) {
        int a = 0;
        for (int i = 0; i < nblk; i++) { int t = s[i]; s[i] = a; a += t; }
    }
    __syncthreads();
    if (tid < nblk) g_blksum[tid] = s[tid];
}

__global__ void scan3_kernel(int n, int e) {
    int i = blockIdx.x * blockDim.x + threadIdx.x;
    if (i < n) {
        int v = g_excl[i] + g_blksum[i >> 10];
        g_rowptr[i] = v;
        g_cursor[i] = v;
    }
    if (i == 0) g_rowptr[n] = e;
}

__global__ void scatter_kernel(const int* __restrict__ ei, int e, int n) {
    int i = blockIdx.x * blockDim.x + threadIdx.x;
    if (i < e) {
        int r = ei[i];
        int c = ei[(size_t)e + i];
        if ((unsigned)r >= (unsigned)n || (unsigned)c >= (unsigned)n) return;
        float w = -g_dis[r] * g_dis[c];
        int pos = atomicAdd(&g_cursor[c], 1);
        g_csr_src[pos] = r;
        g_csr_w[pos] = w;
    }
}

// coe[i] = 2/(K+1) * sum_j T_i(x_j) * temp[j]
__global__ void coef_kernel(const float* __restrict__ temp) {
    if (blockIdx.x == 0 && threadIdx.x == 0) {
        double acc[KCH + 1];
        for (int i = 0; i <= KCH; i++) acc[i] = 0.0;
        for (int j = 0; j <= KCH; j++) {
            double xj = cos(((double)(KCH - j) + 0.5) * M_PI / (double)(KCH + 1));
            double tj = (double)temp[j];
            double t0 = 1.0, t1 = xj;
            acc[0] += t0 * tj;
            acc[1] += t1 * tj;
            for (int i = 2; i <= KCH; i++) {
                double t2 = 2.0 * xj * t1 - t0;
                acc[i] += t2 * tj;
                t0 = t1; t1 = t2;
            }
        }
        for (int i = 0; i <= KCH; i++)
            g_coe[i] = (float)(acc[i] * 2.0 / (double)(KCH + 1));
    }
}

// ---------------- propagation (pull CSR, one warp per dst, float2/lane) ------
__device__ __forceinline__ void prop_accum(const float2* __restrict__ v2,
                                           int s, int e, int lane,
                                           float& ax, float& ay)
{
    int i = s;
    for (; i + 4 <= e; i += 4) {
        int   s0 = g_csr_src[i + 0], s1 = g_csr_src[i + 1];
        int   s2 = g_csr_src[i + 2], s3 = g_csr_src[i + 3];
        float w0 = g_csr_w[i + 0],   w1 = g_csr_w[i + 1];
        float w2 = g_csr_w[i + 2],   w3 = g_csr_w[i + 3];
        float2 x0 = v2[s0 * 32 + lane];
        float2 x1 = v2[s1 * 32 + lane];
        float2 x2 = v2[s2 * 32 + lane];
        float2 x3 = v2[s3 * 32 + lane];
        ax = fmaf(w0, x0.x, ax); ay = fmaf(w0, x0.y, ay);
        ax = fmaf(w1, x1.x, ax); ay = fmaf(w1, x1.y, ay);
        ax = fmaf(w2, x2.x, ax); ay = fmaf(w2, x2.y, ay);
        ax = fmaf(w3, x3.x, ax); ay = fmaf(w3, x3.y, ay);
    }
    for (; i < e; i++) {
        int s0 = g_csr_src[i];
        float w0 = g_csr_w[i];
        float2 x0 = v2[s0 * 32 + lane];
        ax = fmaf(w0, x0.x, ax); ay = fmaf(w0, x0.y, ay);
    }
}

// Tx1 = prop(h);  out = coe0/2 * h + coe1 * Tx1
__global__ __launch_bounds__(256) void prop_first_kernel(int n, float2* __restrict__ out) {
    int g = threadIdx.x >> 5, lane = threadIdx.x & 31;
    int dst = (blockIdx.x << 3) + g;
    if (dst >= n) return;
    const float2* __restrict__ v2 = (const float2*)g_buf0;
    int s = g_rowptr[dst], e = g_rowptr[dst + 1];
    float ax = 0.f, ay = 0.f;
    prop_accum(v2, s, e, lane, ax, ay);
    int idx = dst * 32 + lane;
    float2 h0 = v2[idx];
    ((float2*)g_buf1)[idx] = make_float2(ax, ay);
    float c0 = 0.5f * g_coe[0], c1 = g_coe[1];
    out[idx] = make_float2(fmaf(c0, h0.x, c1 * ax), fmaf(c0, h0.y, c1 * ay));
}

// Tx2 = 2*prop(Tx1) - Tx0;  out += coe[i]*Tx2
__global__ __launch_bounds__(256) void prop_step_kernel(int n, float2* __restrict__ out,
                                                        int iv, int it0, int it2, int ci) {
    int g = threadIdx.x >> 5, lane = threadIdx.x & 31;
    int dst = (blockIdx.x << 3) + g;
    if (dst >= n) return;
    const float2* __restrict__ v2 = (const float2*)bufptr(iv);
    const float2* __restrict__ t0 = (const float2*)bufptr(it0);
    float2* __restrict__ t2 = (float2*)bufptr(it2);
    int s = g_rowptr[dst], e = g_rowptr[dst + 1];
    float ax = 0.f, ay = 0.f;
    prop_accum(v2, s, e, lane, ax, ay);
    int idx = dst * 32 + lane;
    float2 p0 = t0[idx];
    float2 nt = make_float2(2.f * ax - p0.x, 2.f * ay - p0.y);
    t2[idx] = nt;
    float coe = g_coe[ci];
    float2 o = out[idx];
    o.x = fmaf(coe, nt.x, o.x);
    o.y = fmaf(coe, nt.y, o.y);
    out[idx] = o;
}

// ---------------- launch ------------------------------------------------------
extern "C" void kernel_launch(void* const* d_in, const int* in_sizes, int n_in,
                              void* d_out, int out_size)
{
    const float* x    = (const float*)d_in[0];
    const int*   ei   = (const int*)d_in[1];
    const float* W1   = (const float*)d_in[2];
    const float* b1   = (const float*)d_in[3];
    const float* W2   = (const float*)d_in[4];
    const float* b2   = (const float*)d_in[5];
    const float* temp = (const float*)d_in[6];
    float2*      out  = (float2*)d_out;

    int n = in_sizes[0] / FIN;   // 100000
    int e = in_sizes[1] / 2;     // 1600000

    zero_kernel<<<(n + 255) / 256, 256>>>(n);
    mlp_kernel<<<(n + 63) / 64, 256>>>(x, W1, b1, W2, b2, n);
    hist_kernel<<<(e + 255) / 256, 256>>>(ei, e, n);
    dis_kernel<<<(n + 255) / 256, 256>>>(n);

    int nblk = (n + 1023) / 1024;
    scan1_kernel<<<nblk, 256>>>(n);
    scan2_kernel<<<1, 256>>>(nblk);
    scan3_kernel<<<(n + 255) / 256, 256>>>(n, e);
    scatter_kernel<<<(e + 255) / 256, 256>>>(ei, e, n);
    coef_kernel<<<1, 32>>>(temp);

    int pblocks = (n + 7) / 8;
    prop_first_kernel<<<pblocks, 256>>>(n, out);
    int i0 = 0, i1 = 1;
    for (int i = 2; i <= KCH; i++) {
        int i2 = 3 - i0 - i1;
        prop_step_kernel<<<pblocks, 256>>>(n, out, i1, i0, i2, i);
        i0 = i1; i1 = i2;
    }
}

// round 3
// speedup vs baseline: 3.9025x; 3.9025x over previous
#include <cuda_runtime.h>
#include <cuda_bf16.h>
#include <math.h>

// Problem constants (fixed shapes per reference)
#define NMAX 100000
#define EMAX 1600000
#define FIN  256
#define HID  64
#define KCH  10

// ---------------- static device scratch (no allocations allowed) -------------
__device__ float g_buf0[NMAX * HID];
__device__ float g_buf1[NMAX * HID];
__device__ float g_buf2[NMAX * HID];

__device__ int   g_deg[NMAX];
__device__ int   g_cnt[NMAX];
__device__ float g_dis[NMAX];
__device__ int   g_excl[NMAX];
__device__ int   g_rowptr[NMAX + 1];
__device__ int   g_cursor[NMAX];
__device__ int   g_blksum[256];
__device__ int2  g_csr[EMAX];          // packed {src, float_as_int(w)}
__device__ float g_coe[KCH + 1];
__device__ int   g_skip;               // 1 -> propagation numerically negligible

__device__ __forceinline__ float* bufptr(int i) {
    return (i == 0) ? g_buf0 : ((i == 1) ? g_buf1 : g_buf2);
}

// ---------------- coefficients + skip decision (launched FIRST) --------------
// coe[i] = 2/(K+1) * sum_j T_i(x_j) * temp[j], double precision.
// skip = 1 iff sum_{i>=1} |coe_i| < 1e-8  (then dropping all propagation terms
// introduces norm error <= 1e-8 * sum (i+1) ~ 1e-6 relative — provably safe).
__global__ void coef_kernel(const float* __restrict__ temp) {
    if (blockIdx.x == 0 && threadIdx.x == 0) {
        double acc[KCH + 1];
        for (int i = 0; i <= KCH; i++) acc[i] = 0.0;
        for (int j = 0; j <= KCH; j++) {
            double xj = cos(((double)(KCH - j) + 0.5) * M_PI / (double)(KCH + 1));
            double tj = (double)temp[j];
            double t0 = 1.0, t1 = xj;
            acc[0] += t0 * tj;
            acc[1] += t1 * tj;
            for (int i = 2; i <= KCH; i++) {
                double t2 = 2.0 * xj * t1 - t0;
                acc[i] += t2 * tj;
                t0 = t1; t1 = t2;
            }
        }
        double s = 0.0;
        for (int i = 0; i <= KCH; i++) {
            double c = acc[i] * 2.0 / (double)(KCH + 1);
            g_coe[i] = (float)c;
            if (i >= 1) s += fabs(c);
        }
        g_skip = (s < 1e-8) ? 1 : 0;
    }
}

// ---------------- MLP: h = relu(x@W1 + b1) @ W2 + b2 ------------------------
// Always writes out = (coe0/2) * h. Writes g_buf0 = h only if !skip.
// Also zeroes g_deg / g_cnt (128 ints per block; 1563 blocks cover 200k).
__global__ __launch_bounds__(256) void mlp_kernel(
    const float* __restrict__ x,
    const float* __restrict__ W1, const float* __restrict__ b1,
    const float* __restrict__ W2, const float* __restrict__ b2,
    int n, float* __restrict__ out)
{
    __shared__ float As[16][68];   // [kk][row]
    __shared__ float Ws[16][68];   // [kk][col]
    __shared__ float Hst[64][68];  // [c][row]  (transposed hidden)
    __shared__ float W2s[64][68];  // [c][col]

    const int tid = threadIdx.x;
    const int tx = tid & 15, ty = tid >> 4;
    const int row0 = blockIdx.x * 64;

    // fused zeroing of degree/count arrays (flat 2n ints)
    {
        int zi = blockIdx.x * 128 + (tid >> 1);
        if (tid < 256 && zi < n) {
            if (tid & 1) g_cnt[zi] = 0; else g_deg[zi] = 0;
        }
        int zi2 = blockIdx.x * 128 + 64 + (tid >> 1);
        if (zi2 < n) {
            if (tid & 1) g_cnt[zi2] = 0; else g_deg[zi2] = 0;
        }
    }

    // stage W2 fully
    for (int i = tid; i < 64 * 64; i += 256)
        W2s[i >> 6][i & 63] = W2[i];

    float acc[4][4];
    #pragma unroll
    for (int i = 0; i < 4; i++)
        #pragma unroll
        for (int j = 0; j < 4; j++) acc[i][j] = 0.f;

    for (int k0 = 0; k0 < FIN; k0 += 16) {
        {
            int kk = tid & 15, rb = tid >> 4;
            #pragma unroll
            for (int s = 0; s < 4; s++) {
                int r = rb + s * 16;
                int gr = row0 + r;
                As[kk][r] = (gr < n) ? x[(size_t)gr * FIN + k0 + kk] : 0.f;
            }
        }
        {
            int nn = tid & 63, kb = tid >> 6;
            #pragma unroll
            for (int s = 0; s < 4; s++) {
                int kw = kb + s * 4;
                Ws[kw][nn] = W1[(size_t)(k0 + kw) * HID + nn];
            }
        }
        __syncthreads();
        #pragma unroll
        for (int kk = 0; kk < 16; kk++) {
            float4 a4 = *(const float4*)(&As[kk][ty * 4]);
            float4 b4 = *(const float4*)(&Ws[kk][tx * 4]);
            float av[4] = {a4.x, a4.y, a4.z, a4.w};
            float bv[4] = {b4.x, b4.y, b4.z, b4.w};
            #pragma unroll
            for (int i = 0; i < 4; i++)
                #pragma unroll
                for (int j = 0; j < 4; j++)
                    acc[i][j] = fmaf(av[i], bv[j], acc[i][j]);
        }
        __syncthreads();
    }

    {
        float4 bb = *(const float4*)(&b1[tx * 4]);
        float bv[4] = {bb.x, bb.y, bb.z, bb.w};
        #pragma unroll
        for (int i = 0; i < 4; i++)
            #pragma unroll
            for (int j = 0; j < 4; j++) {
                float v = acc[i][j] + bv[j];
                Hst[tx * 4 + j][ty * 4 + i] = fmaxf(v, 0.f);
            }
    }
    __syncthreads();

    float acc2[4][4];
    #pragma unroll
    for (int i = 0; i < 4; i++)
        #pragma unroll
        for (int j = 0; j < 4; j++) acc2[i][j] = 0.f;

    #pragma unroll 8
    for (int c = 0; c < 64; c++) {
        float4 a4 = *(const float4*)(&Hst[c][ty * 4]);
        float4 b4 = *(const float4*)(&W2s[c][tx * 4]);
        float av[4] = {a4.x, a4.y, a4.z, a4.w};
        float bv[4] = {b4.x, b4.y, b4.z, b4.w};
        #pragma unroll
        for (int i = 0; i < 4; i++)
            #pragma unroll
            for (int j = 0; j < 4; j++)
                acc2[i][j] = fmaf(av[i], bv[j], acc2[i][j]);
    }

    {
        float4 bb = *(const float4*)(&b2[tx * 4]);
        float bv[4] = {bb.x, bb.y, bb.z, bb.w};
        float c0h = 0.5f * g_coe[0];
        int skip = g_skip;
        #pragma unroll
        for (int i = 0; i < 4; i++) {
            int gr = row0 + ty * 4 + i;
            if (gr < n) {
                float4 h4;
                h4.x = acc2[i][0] + bv[0];
                h4.y = acc2[i][1] + bv[1];
                h4.z = acc2[i][2] + bv[2];
                h4.w = acc2[i][3] + bv[3];
                if (!skip)
                    *(float4*)(&g_buf0[(size_t)gr * HID + tx * 4]) = h4;
                float4 o;
                o.x = c0h * h4.x; o.y = c0h * h4.y;
                o.z = c0h * h4.z; o.w = c0h * h4.w;
                *(float4*)(&out[(size_t)gr * HID + tx * 4]) = o;
            }
        }
    }
}

// ---------------- graph preprocessing (all gated on g_skip) ------------------
// edge_index is int32. 4 edges per thread.
__global__ void hist_kernel(const int* __restrict__ ei, int e, int n) {
    if (g_skip) return;
    int base = blockIdx.x * 1024 + threadIdx.x;
    #pragma unroll
    for (int s = 0; s < 4; s++) {
        int i = base + s * 256;
        if (i < e) {
            int r = ei[i];
            int c = ei[(size_t)e + i];
            if ((unsigned)r < (unsigned)n) atomicAdd(&g_deg[r], 1);
            if ((unsigned)c < (unsigned)n) atomicAdd(&g_cnt[c], 1);
        }
    }
}

// exclusive scan pass 1 over g_cnt (+fused dis computation from g_deg)
__global__ __launch_bounds__(256) void scan1_kernel(int n) {
    if (g_skip) return;
    __shared__ int wsum[8];
    int tid = threadIdx.x;
    int lane = tid & 31, wid = tid >> 5;
    int base = blockIdx.x * 1024 + tid * 4;
    int v[4];
    #pragma unroll
    for (int j = 0; j < 4; j++) {
        int idx = base + j;
        v[j] = (idx < n) ? g_cnt[idx] : 0;
        if (idx < n) {
            int d = g_deg[idx];
            g_dis[idx] = (d > 0) ? rsqrtf((float)d) : 0.f;
        }
    }
    int tsum = v[0] + v[1] + v[2] + v[3];

    int sc = tsum;
    #pragma unroll
    for (int off = 1; off < 32; off <<= 1) {
        int t = __shfl_up_sync(0xffffffffu, sc, off);
        if (lane >= off) sc += t;
    }
    if (lane == 31) wsum[wid] = sc;
    __syncthreads();
    if (tid == 0) {
        int a = 0;
        #pragma unroll
        for (int i = 0; i < 8; i++) { int t = wsum[i]; wsum[i] = a; a += t; }
    }
    __syncthreads();
    int run = (sc - tsum) + wsum[wid];
    #pragma unroll
    for (int j = 0; j < 4; j++) {
        if (base + j < n) g_excl[base + j] = run;
        run += v[j];
    }
    if (tid == 255) g_blksum[blockIdx.x] = run;
}

__global__ void scan2_kernel(int nblk) {
    if (g_skip) return;
    __shared__ int s[256];
    int tid = threadIdx.x;
    if (tid < nblk) s[tid] = g_blksum[tid];
    __syncthreads();
    if (tid == 0) {
        int a = 0;
        for (int i = 0; i < nblk; i++) { int t = s[i]; s[i] = a; a += t; }
    }
    __syncthreads();
    if (tid < nblk) g_blksum[tid] = s[tid];
}

__global__ void scan3_kernel(int n, int e) {
    if (g_skip) return;
    int i = blockIdx.x * blockDim.x + threadIdx.x;
    if (i < n) {
        int v = g_excl[i] + g_blksum[i >> 10];
        g_rowptr[i] = v;
        g_cursor[i] = v;
    }
    if (i == 0) g_rowptr[n] = e;
}

__global__ void scatter_kernel(const int* __restrict__ ei, int e, int n) {
    if (g_skip) return;
    int base = blockIdx.x * 1024 + threadIdx.x;
    #pragma unroll
    for (int s = 0; s < 4; s++) {
        int i = base + s * 256;
        if (i < e) {
            int r = ei[i];
            int c = ei[(size_t)e + i];
            if ((unsigned)r >= (unsigned)n || (unsigned)c >= (unsigned)n) continue;
            float w = -g_dis[r] * g_dis[c];
            int pos = atomicAdd(&g_cursor[c], 1);
            g_csr[pos] = make_int2(r, __float_as_int(w));
        }
    }
}

// ---------------- propagation (pull CSR, warp per dst, 4 dsts/warp) ----------
__device__ __forceinline__ void prop_accum(const float2* __restrict__ v2,
                                           int s, int e, int lane,
                                           float& ax, float& ay)
{
    int i = s;
    for (; i + 4 <= e; i += 4) {
        int2 e0 = g_csr[i + 0], e1 = g_csr[i + 1];
        int2 e2 = g_csr[i + 2], e3 = g_csr[i + 3];
        float2 x0 = v2[e0.x * 32 + lane];
        float2 x1 = v2[e1.x * 32 + lane];
        float2 x2 = v2[e2.x * 32 + lane];
        float2 x3 = v2[e3.x * 32 + lane];
        float w0 = __int_as_float(e0.y), w1 = __int_as_float(e1.y);
        float w2 = __int_as_float(e2.y), w3 = __int_as_float(e3.y);
        ax = fmaf(w0, x0.x, ax); ay = fmaf(w0, x0.y, ay);
        ax = fmaf(w1, x1.x, ax); ay = fmaf(w1, x1.y, ay);
        ax = fmaf(w2, x2.x, ax); ay = fmaf(w2, x2.y, ay);
        ax = fmaf(w3, x3.x, ax); ay = fmaf(w3, x3.y, ay);
    }
    for (; i < e; i++) {
        int2 e0 = g_csr[i];
        float w0 = __int_as_float(e0.y);
        float2 x0 = v2[e0.x * 32 + lane];
        ax = fmaf(w0, x0.x, ax); ay = fmaf(w0, x0.y, ay);
    }
}

// Tx1 = prop(h);  out += coe1 * Tx1   (out already holds coe0/2 * h)
__global__ __launch_bounds__(256) void prop_first_kernel(int n, float2* __restrict__ out) {
    if (g_skip) return;
    int warp = threadIdx.x >> 5, lane = threadIdx.x & 31;
    int dst0 = (blockIdx.x * 8 + warp) * 4;
    const float2* __restrict__ v2 = (const float2*)g_buf0;
    float c1 = g_coe[1];
    #pragma unroll
    for (int t = 0; t < 4; t++) {
        int dst = dst0 + t;
        if (dst >= n) return;
        int s = g_rowptr[dst], e = g_rowptr[dst + 1];
        float ax = 0.f, ay = 0.f;
        prop_accum(v2, s, e, lane, ax, ay);
        int idx = dst * 32 + lane;
        ((float2*)g_buf1)[idx] = make_float2(ax, ay);
        float2 o = out[idx];
        o.x = fmaf(c1, ax, o.x);
        o.y = fmaf(c1, ay, o.y);
        out[idx] = o;
    }
}

// Tx2 = 2*prop(Tx1) - Tx0;  out += coe[i]*Tx2
__global__ __launch_bounds__(256) void prop_step_kernel(int n, float2* __restrict__ out,
                                                        int iv, int it0, int it2, int ci) {
    if (g_skip) return;
    int warp = threadIdx.x >> 5, lane = threadIdx.x & 31;
    int dst0 = (blockIdx.x * 8 + warp) * 4;
    const float2* __restrict__ v2 = (const float2*)bufptr(iv);
    const float2* __restrict__ t0 = (const float2*)bufptr(it0);
    float2* __restrict__ t2 = (float2*)bufptr(it2);
    float coe = g_coe[ci];
    #pragma unroll
    for (int t = 0; t < 4; t++) {
        int dst = dst0 + t;
        if (dst >= n) return;
        int s = g_rowptr[dst], e = g_rowptr[dst + 1];
        float ax = 0.f, ay = 0.f;
        prop_accum(v2, s, e, lane, ax, ay);
        int idx = dst * 32 + lane;
        float2 p0 = t0[idx];
        float2 nt = make_float2(2.f * ax - p0.x, 2.f * ay - p0.y);
        t2[idx] = nt;
        float2 o = out[idx];
        o.x = fmaf(coe, nt.x, o.x);
        o.y = fmaf(coe, nt.y, o.y);
        out[idx] = o;
    }
}

// ---------------- launch ------------------------------------------------------
extern "C" void kernel_launch(void* const* d_in, const int* in_sizes, int n_in,
                              void* d_out, int out_size)
{
    const float* x    = (const float*)d_in[0];
    const int*   ei   = (const int*)d_in[1];
    const float* W1   = (const float*)d_in[2];
    const float* b1   = (const float*)d_in[3];
    const float* W2   = (const float*)d_in[4];
    const float* b2   = (const float*)d_in[5];
    const float* temp = (const float*)d_in[6];
    float*       out  = (float*)d_out;

    int n = in_sizes[0] / FIN;   // 100000
    int e = in_sizes[1] / 2;     // 1600000

    coef_kernel<<<1, 32>>>(temp);
    mlp_kernel<<<(n + 63) / 64, 256>>>(x, W1, b1, W2, b2, n, out);
    hist_kernel<<<(e + 1023) / 1024, 256>>>(ei, e, n);

    int nblk = (n + 1023) / 1024;
    scan1_kernel<<<nblk, 256>>>(n);
    scan2_kernel<<<1, 256>>>(nblk);
    scan3_kernel<<<(n + 255) / 256, 256>>>(n, e);
    scatter_kernel<<<(e + 1023) / 1024, 256>>>(ei, e, n);

    int pblocks = (n + 31) / 32;
    prop_first_kernel<<<pblocks, 256>>>(n, (float2*)out);
    int i0 = 0, i1 = 1;
    for (int i = 2; i <= KCH; i++) {
        int i2 = 3 - i0 - i1;
        prop_step_kernel<<<pblocks, 256>>>(n, (float2*)out, i1, i0, i2, i);
        i0 = i1; i1 = i2;
    }
}

// round 4
// speedup vs baseline: 7.4365x; 1.9056x over previous
#include <cuda_runtime.h>
#include <cuda_bf16.h>
#include <math.h>
#include <stdint.h>

// Problem constants (fixed shapes per reference)
#define NMAX 100000
#define EMAX 1600000
#define FIN  256
#define HID  64
#define KCH  10
#define SP   72          // smem row stride in bf16 elems (144B, LDSM conflict-free)
#define PGRID 148        // persistent grid: 1 block/SM guaranteed co-resident

// ---------------- static device scratch (no allocations allowed) -------------
__device__ float g_buf0[NMAX * HID];
__device__ float g_buf1[NMAX * HID];
__device__ float g_buf2[NMAX * HID];

__device__ int   g_deg[NMAX];
__device__ int   g_cnt[NMAX];
__device__ float g_dis[NMAX];
__device__ int   g_excl[NMAX];
__device__ int   g_rowptr[NMAX + 1];
__device__ int   g_cursor[NMAX];
__device__ int   g_blksum[256];
__device__ int2  g_csr[EMAX];          // packed {src, float_as_int(w)}
__device__ float g_coe[KCH + 1];
__device__ int   g_skip;               // 1 -> propagation numerically negligible

// global barrier state (only touched in non-skip path)
__device__ volatile unsigned g_gen;
__device__ unsigned g_cntbar;

__device__ __forceinline__ float* bufptr(int i) {
    return (i == 0) ? g_buf0 : ((i == 1) ? g_buf1 : g_buf2);
}

// sense-reversing grid barrier; all blocks of the (co-resident) grid must call.
__device__ __forceinline__ void gbar() {
    __syncthreads();
    if (threadIdx.x == 0) {
        unsigned gen = g_gen;
        __threadfence();
        if (atomicAdd(&g_cntbar, 1u) == gridDim.x - 1) {
            g_cntbar = 0;
            __threadfence();
            g_gen = gen + 1;
        } else {
            while (g_gen == gen) { __nanosleep(32); }
            __threadfence();
        }
    }
    __syncthreads();
}

// ---------------- coefficients + skip decision (launched FIRST) --------------
__global__ void coef_kernel(const float* __restrict__ temp) {
    if (blockIdx.x == 0 && threadIdx.x == 0) {
        double acc[KCH + 1];
        for (int i = 0; i <= KCH; i++) acc[i] = 0.0;
        for (int j = 0; j <= KCH; j++) {
            double xj = cos(((double)(KCH - j) + 0.5) * M_PI / (double)(KCH + 1));
            double tj = (double)temp[j];
            double t0 = 1.0, t1 = xj;
            acc[0] += t0 * tj;
            acc[1] += t1 * tj;
            for (int i = 2; i <= KCH; i++) {
                double t2 = 2.0 * xj * t1 - t0;
                acc[i] += t2 * tj;
                t0 = t1; t1 = t2;
            }
        }
        double s = 0.0;
        for (int i = 0; i <= KCH; i++) {
            double c = acc[i] * 2.0 / (double)(KCH + 1);
            g_coe[i] = (float)c;
            if (i >= 1) s += fabs(c);
        }
        g_skip = (s < 1e-8) ? 1 : 0;
    }
}

// ---------------- tensor-core helpers ----------------------------------------
__device__ __forceinline__ uint32_t smem_u32(const void* p) {
    return (uint32_t)__cvta_generic_to_shared(p);
}
__device__ __forceinline__ void ldsm4(uint32_t r[4], uint32_t a) {
    asm volatile("ldmatrix.sync.aligned.m8n8.x4.shared.b16 {%0,%1,%2,%3},[%4];"
        : "=r"(r[0]), "=r"(r[1]), "=r"(r[2]), "=r"(r[3]) : "r"(a));
}
__device__ __forceinline__ void ldsm4t(uint32_t r[4], uint32_t a) {
    asm volatile("ldmatrix.sync.aligned.m8n8.x4.trans.shared.b16 {%0,%1,%2,%3},[%4];"
        : "=r"(r[0]), "=r"(r[1]), "=r"(r[2]), "=r"(r[3]) : "r"(a));
}
__device__ __forceinline__ void mma_bf16(float c[4], const uint32_t a[4],
                                         uint32_t b0, uint32_t b1) {
    asm volatile("mma.sync.aligned.m16n8k16.row.col.f32.bf16.bf16.f32 "
        "{%0,%1,%2,%3},{%4,%5,%6,%7},{%8,%9},{%0,%1,%2,%3};"
        : "+f"(c[0]), "+f"(c[1]), "+f"(c[2]), "+f"(c[3])
        : "r"(a[0]), "r"(a[1]), "r"(a[2]), "r"(a[3]), "r"(b0), "r"(b1));
}
// split fp32 pair into bf16 hi/lo planes at smem index idx (idx even)
__device__ __forceinline__ void store_pair(__nv_bfloat16* hi, __nv_bfloat16* lo,
                                           int idx, float a, float b) {
    __nv_bfloat16 ha = __float2bfloat16_rn(a), hb = __float2bfloat16_rn(b);
    __nv_bfloat16 la = __float2bfloat16_rn(a - __bfloat162float(ha));
    __nv_bfloat16 lb = __float2bfloat16_rn(b - __bfloat162float(hb));
    *(__nv_bfloat162*)(hi + idx) = __halves2bfloat162(ha, hb);
    *(__nv_bfloat162*)(lo + idx) = __halves2bfloat162(la, lb);
}

// ---------------- MLP on tensor cores (bf16 hi/lo 3-term split) --------------
// out = (coe0/2) * h always; g_buf0 = h only if !skip.
// Block: 128 rows, 8 warps; warp w owns m-rows [16w,16w+16), full N=64.
__global__ __launch_bounds__(256, 2) void mlp_tc_kernel(
    const float* __restrict__ x,
    const float* __restrict__ W1, const float* __restrict__ b1,
    const float* __restrict__ W2, const float* __restrict__ b2,
    int n, float* __restrict__ out)
{
    extern __shared__ __nv_bfloat16 sm[];
    __nv_bfloat16* sXhi = sm;                 // [128][SP]  (X chunk, later H)
    __nv_bfloat16* sXlo = sXhi + 128 * SP;
    __nv_bfloat16* sWhi = sXlo + 128 * SP;    // [64][SP]   (W1 chunk, later W2)
    __nv_bfloat16* sWlo = sWhi + 64 * SP;

    const int tid = threadIdx.x, lane = tid & 31, warp = tid >> 5;
    const int row0 = blockIdx.x * 128;
    const int m0 = warp * 16;

    float c1[8][4];
    #pragma unroll
    for (int i = 0; i < 8; i++)
        #pragma unroll
        for (int j = 0; j < 4; j++) c1[i][j] = 0.f;

    // A ldmatrix lane addressing: row = m0 + lane%16, 16B-half = lane/16
    const int arow = m0 + (lane & 15);
    const uint32_t aoff = (uint32_t)(lane >> 4) * 16;
    const uint32_t aBaseHi = smem_u32(sXhi + arow * SP) + aoff;
    const uint32_t aBaseLo = smem_u32(sXlo + arow * SP) + aoff;
    // B ldmatrix.trans lane addressing (k-major smem):
    // threads 0-7: k0..7 @n0 | 8-15: k8..15 @n0 | 16-23: k0..7 @n0+8 | 24-31: k8..15 @n0+8
    const int brow = (lane & 7) + ((lane >> 3) & 1) * 8;
    const int bcol = (lane >> 4) * 8;
    const uint32_t bBaseHi = smem_u32(sWhi) + (uint32_t)(brow * SP + bcol) * 2;
    const uint32_t bBaseLo = smem_u32(sWlo) + (uint32_t)(brow * SP + bcol) * 2;

    const int xr = tid >> 1, xh = tid & 1;        // X loader: row, 32-col half
    const int wr = tid >> 2, wq = tid & 3;        // W loader: row, 16-col quarter

    // ---- GEMM1: K=256 in 4 chunks of 64 ----
    for (int c = 0; c < 4; c++) {
        {   // stage X chunk [128][64] -> hi/lo
            int gr = row0 + xr;
            const float4* src = (const float4*)(x + (size_t)gr * FIN + c * 64 + xh * 32);
            int colb = xr * SP + xh * 32;
            #pragma unroll
            for (int j = 0; j < 8; j++) {
                float4 v = (gr < n) ? src[j] : make_float4(0.f, 0.f, 0.f, 0.f);
                store_pair(sXhi, sXlo, colb + j * 4,     v.x, v.y);
                store_pair(sXhi, sXlo, colb + j * 4 + 2, v.z, v.w);
            }
        }
        {   // stage W1 chunk [64][64] -> hi/lo
            const float4* src = (const float4*)(W1 + (size_t)(c * 64 + wr) * HID + wq * 16);
            int colb = wr * SP + wq * 16;
            #pragma unroll
            for (int j = 0; j < 4; j++) {
                float4 v = src[j];
                store_pair(sWhi, sWlo, colb + j * 4,     v.x, v.y);
                store_pair(sWhi, sWlo, colb + j * 4 + 2, v.z, v.w);
            }
        }
        __syncthreads();
        #pragma unroll
        for (int ks = 0; ks < 4; ks++) {
            uint32_t ahi[4], alo[4];
            ldsm4(ahi, aBaseHi + ks * 32);
            ldsm4(alo, aBaseLo + ks * 32);
            uint32_t kadd = (uint32_t)(ks * 16 * SP) * 2;
            #pragma unroll
            for (int ntp = 0; ntp < 4; ntp++) {
                uint32_t bhi[4], blo[4];
                ldsm4t(bhi, bBaseHi + kadd + ntp * 32);
                ldsm4t(blo, bBaseLo + kadd + ntp * 32);
                mma_bf16(c1[2 * ntp],     ahi, bhi[0], bhi[1]);
                mma_bf16(c1[2 * ntp],     ahi, blo[0], blo[1]);
                mma_bf16(c1[2 * ntp],     alo, bhi[0], bhi[1]);
                mma_bf16(c1[2 * ntp + 1], ahi, bhi[2], bhi[3]);
                mma_bf16(c1[2 * ntp + 1], ahi, blo[2], blo[3]);
                mma_bf16(c1[2 * ntp + 1], alo, bhi[2], bhi[3]);
            }
        }
        __syncthreads();
    }

    // ---- transition: stage W2, store H = relu(c1 + b1) into sX planes ----
    {
        const float4* src = (const float4*)(W2 + (size_t)wr * HID + wq * 16);
        int colb = wr * SP + wq * 16;
        #pragma unroll
        for (int j = 0; j < 4; j++) {
            float4 v = src[j];
            store_pair(sWhi, sWlo, colb + j * 4,     v.x, v.y);
            store_pair(sWhi, sWlo, colb + j * 4 + 2, v.z, v.w);
        }
    }
    const int g = lane >> 2, tq = lane & 3;
    {
        const float2* b1f2 = (const float2*)b1;
        #pragma unroll
        for (int nt = 0; nt < 8; nt++) {
            float2 bb = b1f2[nt * 4 + tq];
            int col = nt * 8 + tq * 2;
            float v0 = fmaxf(c1[nt][0] + bb.x, 0.f);
            float v1 = fmaxf(c1[nt][1] + bb.y, 0.f);
            float v2 = fmaxf(c1[nt][2] + bb.x, 0.f);
            float v3 = fmaxf(c1[nt][3] + bb.y, 0.f);
            store_pair(sXhi, sXlo, (m0 + g) * SP + col,     v0, v1);
            store_pair(sXhi, sXlo, (m0 + g + 8) * SP + col, v2, v3);
        }
    }
    __syncthreads();

    // ---- GEMM2: H[128][64] @ W2[64][64] ----
    float c2[8][4];
    #pragma unroll
    for (int i = 0; i < 8; i++)
        #pragma unroll
        for (int j = 0; j < 4; j++) c2[i][j] = 0.f;

    #pragma unroll
    for (int ks = 0; ks < 4; ks++) {
        uint32_t ahi[4], alo[4];
        ldsm4(ahi, aBaseHi + ks * 32);
        ldsm4(alo, aBaseLo + ks * 32);
        uint32_t kadd = (uint32_t)(ks * 16 * SP) * 2;
        #pragma unroll
        for (int ntp = 0; ntp < 4; ntp++) {
            uint32_t bhi[4], blo[4];
            ldsm4t(bhi, bBaseHi + kadd + ntp * 32);
            ldsm4t(blo, bBaseLo + kadd + ntp * 32);
            mma_bf16(c2[2 * ntp],     ahi, bhi[0], bhi[1]);
            mma_bf16(c2[2 * ntp],     ahi, blo[0], blo[1]);
            mma_bf16(c2[2 * ntp],     alo, bhi[0], bhi[1]);
            mma_bf16(c2[2 * ntp + 1], ahi, bhi[2], bhi[3]);
            mma_bf16(c2[2 * ntp + 1], ahi, blo[2], blo[3]);
            mma_bf16(c2[2 * ntp + 1], alo, bhi[2], bhi[3]);
        }
    }

    // ---- epilogue: h2 = c2 + b2;  out = (coe0/2)*h2;  g_buf0 = h2 if !skip ----
    {
        const float2* b2f2 = (const float2*)b2;
        float c0h = 0.5f * g_coe[0];
        int skip = g_skip;
        #pragma unroll
        for (int nt = 0; nt < 8; nt++) {
            float2 bb = b2f2[nt * 4 + tq];
            int col = nt * 8 + tq * 2;
            int r0 = row0 + m0 + g, r1 = r0 + 8;
            if (r0 < n) {
                float2 h2 = make_float2(c2[nt][0] + bb.x, c2[nt][1] + bb.y);
                if (!skip) *(float2*)(g_buf0 + (size_t)r0 * HID + col) = h2;
                *(float2*)(out + (size_t)r0 * HID + col) = make_float2(c0h * h2.x, c0h * h2.y);
            }
            if (r1 < n) {
                float2 h2 = make_float2(c2[nt][2] + bb.x, c2[nt][3] + bb.y);
                if (!skip) *(float2*)(g_buf0 + (size_t)r1 * HID + col) = h2;
                *(float2*)(out + (size_t)r1 * HID + col) = make_float2(c0h * h2.x, c0h * h2.y);
            }
        }
    }
}

// ---------------- persistent preprocessing (gated on g_skip) -----------------
// zero -> hist -> per-chunk scan(+dis) -> blksum scan -> rowptr -> scatter
__global__ __launch_bounds__(256) void prep_persist(const int* __restrict__ ei, int e, int n) {
    if (g_skip) return;
    __shared__ int wsum[8];
    __shared__ int s2[256];
    const int tid = threadIdx.x;
    const int gtid = blockIdx.x * 256 + tid;
    const int gsz = gridDim.x * 256;

    // phase 0: zero
    for (int i = gtid; i < n; i += gsz) { g_deg[i] = 0; g_cnt[i] = 0; }
    gbar();
    // phase 1: histogram
    for (int i = gtid; i < e; i += gsz) {
        int r = ei[i];
        int c = ei[(size_t)e + i];
        if ((unsigned)r < (unsigned)n) atomicAdd(&g_deg[r], 1);
        if ((unsigned)c < (unsigned)n) atomicAdd(&g_cnt[c], 1);
    }
    gbar();
    // phase 2a: per-1024-chunk exclusive scan of g_cnt + fused dis
    int nchunk = (n + 1023) >> 10;
    for (int chunk = blockIdx.x; chunk < nchunk; chunk += gridDim.x) {
        int lane = tid & 31, wid = tid >> 5;
        int base = chunk * 1024 + tid * 4;
        int v[4];
        #pragma unroll
        for (int j = 0; j < 4; j++) {
            int idx = base + j;
            v[j] = (idx < n) ? g_cnt[idx] : 0;
            if (idx < n) {
                int d = g_deg[idx];
                g_dis[idx] = (d > 0) ? rsqrtf((float)d) : 0.f;
            }
        }
        int tsum = v[0] + v[1] + v[2] + v[3];
        int sc = tsum;
        #pragma unroll
        for (int off = 1; off < 32; off <<= 1) {
            int t = __shfl_up_sync(0xffffffffu, sc, off);
            if (lane >= off) sc += t;
        }
        if (lane == 31) wsum[wid] = sc;
        __syncthreads();
        if (tid == 0) {
            int a = 0;
            #pragma unroll
            for (int i = 0; i < 8; i++) { int t = wsum[i]; wsum[i] = a; a += t; }
        }
        __syncthreads();
        int run = (sc - tsum) + wsum[wid];
        #pragma unroll
        for (int j = 0; j < 4; j++) {
            if (base + j < n) g_excl[base + j] = run;
            run += v[j];
        }
        if (tid == 255) g_blksum[chunk] = run;
        __syncthreads();
    }
    gbar();
    // phase 2b: scan chunk sums (block 0)
    if (blockIdx.x == 0) {
        if (tid < nchunk) s2[tid] = g_blksum[tid];
        __syncthreads();
        if (tid == 0) {
            int a = 0;
            for (int i = 0; i < nchunk; i++) { int t = s2[i]; s2[i] = a; a += t; }
        }
        __syncthreads();
        if (tid < nchunk) g_blksum[tid] = s2[tid];
    }
    gbar();
    // phase 2c: rowptr/cursor
    for (int i = gtid; i < n; i += gsz) {
        int v = g_excl[i] + g_blksum[i >> 10];
        g_rowptr[i] = v;
        g_cursor[i] = v;
    }
    if (gtid == 0) g_rowptr[n] = e;
    gbar();
    // phase 3: scatter into CSR
    for (int i = gtid; i < e; i += gsz) {
        int r = ei[i];
        int c = ei[(size_t)e + i];
        if ((unsigned)r >= (unsigned)n || (unsigned)c >= (unsigned)n) continue;
        float w = -g_dis[r] * g_dis[c];
        int pos = atomicAdd(&g_cursor[c], 1);
        g_csr[pos] = make_int2(r, __float_as_int(w));
    }
}

// ---------------- persistent propagation (gated on g_skip) -------------------
__device__ __forceinline__ void prop_accum(const float2* __restrict__ v2,
                                           int s, int e, int lane,
                                           float& ax, float& ay)
{
    int i = s;
    for (; i + 4 <= e; i += 4) {
        int2 e0 = g_csr[i + 0], e1 = g_csr[i + 1];
        int2 e2 = g_csr[i + 2], e3 = g_csr[i + 3];
        float2 x0 = v2[e0.x * 32 + lane];
        float2 x1 = v2[e1.x * 32 + lane];
        float2 x2 = v2[e2.x * 32 + lane];
        float2 x3 = v2[e3.x * 32 + lane];
        float w0 = __int_as_float(e0.y), w1 = __int_as_float(e1.y);
        float w2 = __int_as_float(e2.y), w3 = __int_as_float(e3.y);
        ax = fmaf(w0, x0.x, ax); ay = fmaf(w0, x0.y, ay);
        ax = fmaf(w1, x1.x, ax); ay = fmaf(w1, x1.y, ay);
        ax = fmaf(w2, x2.x, ax); ay = fmaf(w2, x2.y, ay);
        ax = fmaf(w3, x3.x, ax); ay = fmaf(w3, x3.y, ay);
    }
    for (; i < e; i++) {
        int2 e0 = g_csr[i];
        float w0 = __int_as_float(e0.y);
        float2 x0 = v2[e0.x * 32 + lane];
        ax = fmaf(w0, x0.x, ax); ay = fmaf(w0, x0.y, ay);
    }
}

__global__ __launch_bounds__(256) void prop_persist(int n, float2* __restrict__ out) {
    if (g_skip) return;
    const int lane = threadIdx.x & 31;
    const int gw = blockIdx.x * 8 + (threadIdx.x >> 5);
    const int gwn = gridDim.x * 8;

    // step 1: Tx1 = prop(h); out += coe1 * Tx1
    {
        const float2* v2 = (const float2*)g_buf0;
        float c1 = g_coe[1];
        for (int dst0 = gw * 4; dst0 < n; dst0 += gwn * 4) {
            #pragma unroll
            for (int t = 0; t < 4; t++) {
                int dst = dst0 + t;
                if (dst >= n) break;
                int s = g_rowptr[dst], e = g_rowptr[dst + 1];
                float ax = 0.f, ay = 0.f;
                prop_accum(v2, s, e, lane, ax, ay);
                int idx = dst * 32 + lane;
                ((float2*)g_buf1)[idx] = make_float2(ax, ay);
                float2 o = out[idx];
                o.x = fmaf(c1, ax, o.x);
                o.y = fmaf(c1, ay, o.y);
                out[idx] = o;
            }
        }
    }
    // steps 2..K
    int i0 = 0, i1 = 1;
    for (int i = 2; i <= KCH; i++) {
        gbar();
        int i2 = 3 - i0 - i1;
        const float2* v2 = (const float2*)bufptr(i1);
        const float2* t0 = (const float2*)bufptr(i0);
        float2* t2 = (float2*)bufptr(i2);
        float coe = g_coe[i];
        for (int dst0 = gw * 4; dst0 < n; dst0 += gwn * 4) {
            #pragma unroll
            for (int t = 0; t < 4; t++) {
                int dst = dst0 + t;
                if (dst >= n) break;
                int s = g_rowptr[dst], e = g_rowptr[dst + 1];
                float ax = 0.f, ay = 0.f;
                prop_accum(v2, s, e, lane, ax, ay);
                int idx = dst * 32 + lane;
                float2 p0 = t0[idx];
                float2 nt = make_float2(2.f * ax - p0.x, 2.f * ay - p0.y);
                t2[idx] = nt;
                float2 o = out[idx];
                o.x = fmaf(coe, nt.x, o.x);
                o.y = fmaf(coe, nt.y, o.y);
                out[idx] = o;
            }
        }
        i0 = i1; i1 = i2;
    }
}

// ---------------- launch ------------------------------------------------------
extern "C" void kernel_launch(void* const* d_in, const int* in_sizes, int n_in,
                              void* d_out, int out_size)
{
    const float* x    = (const float*)d_in[0];
    const int*   ei   = (const int*)d_in[1];
    const float* W1   = (const float*)d_in[2];
    const float* b1   = (const float*)d_in[3];
    const float* W2   = (const float*)d_in[4];
    const float* b2   = (const float*)d_in[5];
    const float* temp = (const float*)d_in[6];
    float*       out  = (float*)d_out;

    int n = in_sizes[0] / FIN;   // 100000
    int e = in_sizes[1] / 2;     // 1600000

    const int smem_mlp = (128 * 2 + 64 * 2) * SP * 2;  // 55296 B
    cudaFuncSetAttribute(mlp_tc_kernel, cudaFuncAttributeMaxDynamicSharedMemorySize, smem_mlp);

    coef_kernel<<<1, 32>>>(temp);
    mlp_tc_kernel<<<(n + 127) / 128, 256, smem_mlp>>>(x, W1, b1, W2, b2, n, out);
    prep_persist<<<PGRID, 256>>>(ei, e, n);
    prop_persist<<<PGRID, 256>>>(n, (float2*)out);
}

// round 5
// speedup vs baseline: 10.0473x; 1.3511x over previous
#include <cuda_runtime.h>
#include <cuda_bf16.h>
#include <cuda_fp16.h>
#include <math.h>
#include <stdint.h>

// Problem constants (fixed shapes per reference)
#define NMAX 100000
#define EMAX 1600000
#define FIN  256
#define HID  64
#define KCH  10
#define SP   72          // smem row stride in fp16 elems (144B, LDSM conflict-free)
#define PGRID 148        // persistent grid: 1 block/SM guaranteed co-resident

// ---------------- static device scratch (no allocations allowed) -------------
__device__ float g_buf0[NMAX * HID];
__device__ float g_buf1[NMAX * HID];
__device__ float g_buf2[NMAX * HID];

__device__ int   g_deg[NMAX];
__device__ int   g_cnt[NMAX];
__device__ float g_dis[NMAX];
__device__ int   g_excl[NMAX];
__device__ int   g_rowptr[NMAX + 1];
__device__ int   g_cursor[NMAX];
__device__ int   g_blksum[256];
__device__ int2  g_csr[EMAX];          // packed {src, float_as_int(w)}
__device__ float g_coe[KCH + 1];
__device__ int   g_skip;               // 1 -> propagation numerically negligible

// global barrier state (only touched in non-skip path)
__device__ volatile unsigned g_gen;
__device__ unsigned g_cntbar;

__device__ __forceinline__ float* bufptr(int i) {
    return (i == 0) ? g_buf0 : ((i == 1) ? g_buf1 : g_buf2);
}

// sense-reversing grid barrier; all blocks of the (co-resident) grid must call.
__device__ __forceinline__ void gbar() {
    __syncthreads();
    if (threadIdx.x == 0) {
        unsigned gen = g_gen;
        __threadfence();
        if (atomicAdd(&g_cntbar, 1u) == gridDim.x - 1) {
            g_cntbar = 0;
            __threadfence();
            g_gen = gen + 1;
        } else {
            while (g_gen == gen) { __nanosleep(32); }
            __threadfence();
        }
    }
    __syncthreads();
}

// ---------------- coefficients + skip decision (parallel over j) -------------
// coe[i] = 2/(K+1) * sum_j T_i(x_j) * temp[j], double precision.
// Lane j owns node x_j; 10-step recurrence; shfl reduction per coefficient.
__global__ void coef_kernel(const float* __restrict__ temp) {
    int j = threadIdx.x;  // 0..31, lanes 0..KCH active
    double tj = (j <= KCH) ? (double)temp[j] : 0.0;
    double xj = cos(((double)(KCH - j) + 0.5) * M_PI / (double)(KCH + 1));
    double acc[KCH + 1];
    double t0 = 1.0, t1 = xj;
    acc[0] = tj;
    acc[1] = xj * tj;
    #pragma unroll
    for (int i = 2; i <= KCH; i++) {
        double t2 = 2.0 * xj * t1 - t0;
        acc[i] = t2 * tj;
        t0 = t1; t1 = t2;
    }
    #pragma unroll
    for (int i = 0; i <= KCH; i++) {
        double s = acc[i];
        #pragma unroll
        for (int off = 16; off > 0; off >>= 1)
            s += __shfl_down_sync(0xffffffffu, s, off);
        acc[i] = s * 2.0 / (double)(KCH + 1);
    }
    if (j == 0) {
        double ssum = 0.0;
        #pragma unroll
        for (int i = 0; i <= KCH; i++) {
            g_coe[i] = (float)acc[i];
            if (i >= 1) ssum += fabs(acc[i]);
        }
        g_skip = (ssum < 1e-8) ? 1 : 0;
    }
}

// ---------------- tensor-core helpers ----------------------------------------
__device__ __forceinline__ uint32_t smem_u32(const void* p) {
    return (uint32_t)__cvta_generic_to_shared(p);
}
__device__ __forceinline__ void ldsm4(uint32_t r[4], uint32_t a) {
    asm volatile("ldmatrix.sync.aligned.m8n8.x4.shared.b16 {%0,%1,%2,%3},[%4];"
        : "=r"(r[0]), "=r"(r[1]), "=r"(r[2]), "=r"(r[3]) : "r"(a));
}
__device__ __forceinline__ void ldsm4t(uint32_t r[4], uint32_t a) {
    asm volatile("ldmatrix.sync.aligned.m8n8.x4.trans.shared.b16 {%0,%1,%2,%3},[%4];"
        : "=r"(r[0]), "=r"(r[1]), "=r"(r[2]), "=r"(r[3]) : "r"(a));
}
__device__ __forceinline__ void mma_f16(float c[4], const uint32_t a[4],
                                        uint32_t b0, uint32_t b1) {
    asm volatile("mma.sync.aligned.m16n8k16.row.col.f32.f16.f16.f32 "
        "{%0,%1,%2,%3},{%4,%5,%6,%7},{%8,%9},{%0,%1,%2,%3};"
        : "+f"(c[0]), "+f"(c[1]), "+f"(c[2]), "+f"(c[3])
        : "r"(a[0]), "r"(a[1]), "r"(a[2]), "r"(a[3]), "r"(b0), "r"(b1));
}

// ---------------- MLP on tensor cores (fp16 single-pass) ---------------------
// out = (coe0/2) * h always; g_buf0 = h only if !skip.
// Block: 128 rows, 8 warps; warp w owns m-rows [16w,16w+16), full N=64.
__global__ __launch_bounds__(256, 3) void mlp_tc_kernel(
    const float* __restrict__ x,
    const float* __restrict__ W1, const float* __restrict__ b1,
    const float* __restrict__ W2, const float* __restrict__ b2,
    int n, float* __restrict__ out)
{
    extern __shared__ __half sm[];
    __half* sX = sm;               // [128][SP]  (X chunk, later H)
    __half* sW = sm + 128 * SP;    // [64][SP]   (W1 chunk, later W2)

    const int tid = threadIdx.x, lane = tid & 31, warp = tid >> 5;
    const int row0 = blockIdx.x * 128;
    const int m0 = warp * 16;

    float c1[8][4];
    #pragma unroll
    for (int i = 0; i < 8; i++)
        #pragma unroll
        for (int j = 0; j < 4; j++) c1[i][j] = 0.f;

    // A ldmatrix lane addressing: row = m0 + lane%16, 16B-half = lane/16
    const int arow = m0 + (lane & 15);
    const uint32_t aBase = smem_u32(sX + arow * SP) + (uint32_t)(lane >> 4) * 16;
    // B ldmatrix.trans lane addressing (k-major smem)
    const int brow = (lane & 7) + ((lane >> 3) & 1) * 8;
    const int bcol = (lane >> 4) * 8;
    const uint32_t bBase = smem_u32(sW) + (uint32_t)(brow * SP + bcol) * 2;

    const int xr = tid >> 1, xh = tid & 1;        // X loader: row, 32-col half
    const int wr = tid >> 2, wq = tid & 3;        // W loader: row, 16-col quarter

    // ---- GEMM1: K=256 in 4 chunks of 64 ----
    for (int c = 0; c < 4; c++) {
        {   // stage X chunk [128][64] -> fp16
            int gr = row0 + xr;
            const float4* src = (const float4*)(x + (size_t)gr * FIN + c * 64 + xh * 32);
            __half* dst = sX + xr * SP + xh * 32;
            #pragma unroll
            for (int j = 0; j < 8; j++) {
                float4 v = (gr < n) ? src[j] : make_float4(0.f, 0.f, 0.f, 0.f);
                union { __half2 h[2]; uint2 u; } p;
                p.h[0] = __floats2half2_rn(v.x, v.y);
                p.h[1] = __floats2half2_rn(v.z, v.w);
                *(uint2*)(dst + j * 4) = p.u;
            }
        }
        {   // stage W1 chunk [64][64] -> fp16
            const float4* src = (const float4*)(W1 + (size_t)(c * 64 + wr) * HID + wq * 16);
            __half* dst = sW + wr * SP + wq * 16;
            #pragma unroll
            for (int j = 0; j < 4; j++) {
                float4 v = src[j];
                union { __half2 h[2]; uint2 u; } p;
                p.h[0] = __floats2half2_rn(v.x, v.y);
                p.h[1] = __floats2half2_rn(v.z, v.w);
                *(uint2*)(dst + j * 4) = p.u;
            }
        }
        __syncthreads();
        #pragma unroll
        for (int ks = 0; ks < 4; ks++) {
            uint32_t a[4];
            ldsm4(a, aBase + ks * 32);
            uint32_t kadd = (uint32_t)(ks * 16 * SP) * 2;
            #pragma unroll
            for (int ntp = 0; ntp < 4; ntp++) {
                uint32_t b[4];
                ldsm4t(b, bBase + kadd + ntp * 32);
                mma_f16(c1[2 * ntp],     a, b[0], b[1]);
                mma_f16(c1[2 * ntp + 1], a, b[2], b[3]);
            }
        }
        __syncthreads();
    }

    // ---- transition: stage W2, store H = relu(c1 + b1) into sX -------------
    {
        const float4* src = (const float4*)(W2 + (size_t)wr * HID + wq * 16);
        __half* dst = sW + wr * SP + wq * 16;
        #pragma unroll
        for (int j = 0; j < 4; j++) {
            float4 v = src[j];
            union { __half2 h[2]; uint2 u; } p;
            p.h[0] = __floats2half2_rn(v.x, v.y);
            p.h[1] = __floats2half2_rn(v.z, v.w);
            *(uint2*)(dst + j * 4) = p.u;
        }
    }
    const int g = lane >> 2, tq = lane & 3;
    {
        const float2* b1f2 = (const float2*)b1;
        #pragma unroll
        for (int nt = 0; nt < 8; nt++) {
            float2 bb = b1f2[nt * 4 + tq];
            int col = nt * 8 + tq * 2;
            float v0 = fmaxf(c1[nt][0] + bb.x, 0.f);
            float v1 = fmaxf(c1[nt][1] + bb.y, 0.f);
            float v2 = fmaxf(c1[nt][2] + bb.x, 0.f);
            float v3 = fmaxf(c1[nt][3] + bb.y, 0.f);
            *(__half2*)(sX + (m0 + g) * SP + col)     = __floats2half2_rn(v0, v1);
            *(__half2*)(sX + (m0 + g + 8) * SP + col) = __floats2half2_rn(v2, v3);
        }
    }
    __syncthreads();

    // ---- GEMM2: H[128][64] @ W2[64][64] ----
    float c2[8][4];
    #pragma unroll
    for (int i = 0; i < 8; i++)
        #pragma unroll
        for (int j = 0; j < 4; j++) c2[i][j] = 0.f;

    #pragma unroll
    for (int ks = 0; ks < 4; ks++) {
        uint32_t a[4];
        ldsm4(a, aBase + ks * 32);
        uint32_t kadd = (uint32_t)(ks * 16 * SP) * 2;
        #pragma unroll
        for (int ntp = 0; ntp < 4; ntp++) {
            uint32_t b[4];
            ldsm4t(b, bBase + kadd + ntp * 32);
            mma_f16(c2[2 * ntp],     a, b[0], b[1]);
            mma_f16(c2[2 * ntp + 1], a, b[2], b[3]);
        }
    }

    // ---- epilogue: h2 = c2 + b2;  out = (coe0/2)*h2;  g_buf0 = h2 if !skip ----
    {
        const float2* b2f2 = (const float2*)b2;
        float c0h = 0.5f * g_coe[0];
        int skip = g_skip;
        #pragma unroll
        for (int nt = 0; nt < 8; nt++) {
            float2 bb = b2f2[nt * 4 + tq];
            int col = nt * 8 + tq * 2;
            int r0 = row0 + m0 + g, r1 = r0 + 8;
            if (r0 < n) {
                float2 h2 = make_float2(c2[nt][0] + bb.x, c2[nt][1] + bb.y);
                if (!skip) *(float2*)(g_buf0 + (size_t)r0 * HID + col) = h2;
                *(float2*)(out + (size_t)r0 * HID + col) = make_float2(c0h * h2.x, c0h * h2.y);
            }
            if (r1 < n) {
                float2 h2 = make_float2(c2[nt][2] + bb.x, c2[nt][3] + bb.y);
                if (!skip) *(float2*)(g_buf0 + (size_t)r1 * HID + col) = h2;
                *(float2*)(out + (size_t)r1 * HID + col) = make_float2(c0h * h2.x, c0h * h2.y);
            }
        }
    }
}

// ---------------- CSR edge accumulation --------------------------------------
__device__ __forceinline__ void prop_accum(const float2* __restrict__ v2,
                                           int s, int e, int lane,
                                           float& ax, float& ay)
{
    int i = s;
    for (; i + 4 <= e; i += 4) {
        int2 e0 = g_csr[i + 0], e1 = g_csr[i + 1];
        int2 e2 = g_csr[i + 2], e3 = g_csr[i + 3];
        float2 x0 = v2[e0.x * 32 + lane];
        float2 x1 = v2[e1.x * 32 + lane];
        float2 x2 = v2[e2.x * 32 + lane];
        float2 x3 = v2[e3.x * 32 + lane];
        float w0 = __int_as_float(e0.y), w1 = __int_as_float(e1.y);
        float w2 = __int_as_float(e2.y), w3 = __int_as_float(e3.y);
        ax = fmaf(w0, x0.x, ax); ay = fmaf(w0, x0.y, ay);
        ax = fmaf(w1, x1.x, ax); ay = fmaf(w1, x1.y, ay);
        ax = fmaf(w2, x2.x, ax); ay = fmaf(w2, x2.y, ay);
        ax = fmaf(w3, x3.x, ax); ay = fmaf(w3, x3.y, ay);
    }
    for (; i < e; i++) {
        int2 e0 = g_csr[i];
        float w0 = __int_as_float(e0.y);
        float2 x0 = v2[e0.x * 32 + lane];
        ax = fmaf(w0, x0.x, ax); ay = fmaf(w0, x0.y, ay);
    }
}

// ---------------- fused persistent preprocessing + propagation ---------------
__global__ __launch_bounds__(256) void prep_prop_persist(
    const int* __restrict__ ei, int e, int n, float2* __restrict__ out)
{
    if (g_skip) return;
    __shared__ int wsum[8];
    __shared__ int s2[256];
    const int tid = threadIdx.x;
    const int gtid = blockIdx.x * 256 + tid;
    const int gsz = gridDim.x * 256;

    // phase 0: zero
    for (int i = gtid; i < n; i += gsz) { g_deg[i] = 0; g_cnt[i] = 0; }
    gbar();
    // phase 1: histogram
    for (int i = gtid; i < e; i += gsz) {
        int r = ei[i];
        int c = ei[(size_t)e + i];
        if ((unsigned)r < (unsigned)n) atomicAdd(&g_deg[r], 1);
        if ((unsigned)c < (unsigned)n) atomicAdd(&g_cnt[c], 1);
    }
    gbar();
    // phase 2a: per-1024-chunk exclusive scan of g_cnt + fused dis
    int nchunk = (n + 1023) >> 10;
    for (int chunk = blockIdx.x; chunk < nchunk; chunk += gridDim.x) {
        int lane = tid & 31, wid = tid >> 5;
        int base = chunk * 1024 + tid * 4;
        int v[4];
        #pragma unroll
        for (int j = 0; j < 4; j++) {
            int idx = base + j;
            v[j] = (idx < n) ? g_cnt[idx] : 0;
            if (idx < n) {
                int d = g_deg[idx];
                g_dis[idx] = (d > 0) ? rsqrtf((float)d) : 0.f;
            }
        }
        int tsum = v[0] + v[1] + v[2] + v[3];
        int sc = tsum;
        #pragma unroll
        for (int off = 1; off < 32; off <<= 1) {
            int t = __shfl_up_sync(0xffffffffu, sc, off);
            if (lane >= off) sc += t;
        }
        if (lane == 31) wsum[wid] = sc;
        __syncthreads();
        if (tid == 0) {
            int a = 0;
            #pragma unroll
            for (int i = 0; i < 8; i++) { int t = wsum[i]; wsum[i] = a; a += t; }
        }
        __syncthreads();
        int run = (sc - tsum) + wsum[wid];
        #pragma unroll
        for (int j = 0; j < 4; j++) {
            if (base + j < n) g_excl[base + j] = run;
            run += v[j];
        }
        if (tid == 255) g_blksum[chunk] = run;
        __syncthreads();
    }
    gbar();
    // phase 2b: scan chunk sums (block 0)
    if (blockIdx.x == 0) {
        if (tid < nchunk) s2[tid] = g_blksum[tid];
        __syncthreads();
        if (tid == 0) {
            int a = 0;
            for (int i = 0; i < nchunk; i++) { int t = s2[i]; s2[i] = a; a += t; }
        }
        __syncthreads();
        if (tid < nchunk) g_blksum[tid] = s2[tid];
    }
    gbar();
    // phase 2c: rowptr/cursor
    for (int i = gtid; i < n; i += gsz) {
        int v = g_excl[i] + g_blksum[i >> 10];
        g_rowptr[i] = v;
        g_cursor[i] = v;
    }
    if (gtid == 0) g_rowptr[n] = e;
    gbar();
    // phase 3: scatter into CSR
    for (int i = gtid; i < e; i += gsz) {
        int r = ei[i];
        int c = ei[(size_t)e + i];
        if ((unsigned)r >= (unsigned)n || (unsigned)c >= (unsigned)n) continue;
        float w = -g_dis[r] * g_dis[c];
        int pos = atomicAdd(&g_cursor[c], 1);
        g_csr[pos] = make_int2(r, __float_as_int(w));
    }
    gbar();

    // ---- propagation: Chebyshev recurrence ----
    const int lane = tid & 31;
    const int gw = blockIdx.x * 8 + (tid >> 5);
    const int gwn = gridDim.x * 8;

    // step 1: Tx1 = prop(h); out += coe1 * Tx1
    {
        const float2* v2 = (const float2*)g_buf0;
        float c1 = g_coe[1];
        for (int dst0 = gw * 4; dst0 < n; dst0 += gwn * 4) {
            #pragma unroll
            for (int t = 0; t < 4; t++) {
                int dst = dst0 + t;
                if (dst >= n) break;
                int s = g_rowptr[dst], e2 = g_rowptr[dst + 1];
                float ax = 0.f, ay = 0.f;
                prop_accum(v2, s, e2, lane, ax, ay);
                int idx = dst * 32 + lane;
                ((float2*)g_buf1)[idx] = make_float2(ax, ay);
                float2 o = out[idx];
                o.x = fmaf(c1, ax, o.x);
                o.y = fmaf(c1, ay, o.y);
                out[idx] = o;
            }
        }
    }
    // steps 2..K
    int i0 = 0, i1 = 1;
    for (int i = 2; i <= KCH; i++) {
        gbar();
        int i2 = 3 - i0 - i1;
        const float2* v2 = (const float2*)bufptr(i1);
        const float2* t0 = (const float2*)bufptr(i0);
        float2* t2 = (float2*)bufptr(i2);
        float coe = g_coe[i];
        for (int dst0 = gw * 4; dst0 < n; dst0 += gwn * 4) {
            #pragma unroll
            for (int t = 0; t < 4; t++) {
                int dst = dst0 + t;
                if (dst >= n) break;
                int s = g_rowptr[dst], e2 = g_rowptr[dst + 1];
                float ax = 0.f, ay = 0.f;
                prop_accum(v2, s, e2, lane, ax, ay);
                int idx = dst * 32 + lane;
                float2 p0 = t0[idx];
                float2 nt = make_float2(2.f * ax - p0.x, 2.f * ay - p0.y);
                t2[idx] = nt;
                float2 o = out[idx];
                o.x = fmaf(coe, nt.x, o.x);
                o.y = fmaf(coe, nt.y, o.y);
                out[idx] = o;
            }
        }
        i0 = i1; i1 = i2;
    }
}

// ---------------- launch ------------------------------------------------------
extern "C" void kernel_launch(void* const* d_in, const int* in_sizes, int n_in,
                              void* d_out, int out_size)
{
    const float* x    = (const float*)d_in[0];
    const int*   ei   = (const int*)d_in[1];
    const float* W1   = (const float*)d_in[2];
    const float* b1   = (const float*)d_in[3];
    const float* W2   = (const float*)d_in[4];
    const float* b2   = (const float*)d_in[5];
    const float* temp = (const float*)d_in[6];
    float*       out  = (float*)d_out;

    int n = in_sizes[0] / FIN;   // 100000
    int e = in_sizes[1] / 2;     // 1600000

    const int smem_mlp = (128 + 64) * SP * (int)sizeof(__half);  // 27648 B

    coef_kernel<<<1, 32>>>(temp);
    mlp_tc_kernel<<<(n + 127) / 128, 256, smem_mlp>>>(x, W1, b1, W2, b2, n, out);
    prep_prop_persist<<<PGRID, 256>>>(ei, e, n, (float2*)out);
}